// round 1
// baseline (speedup 1.0000x reference)
#include <cuda_runtime.h>
#include <math.h>

#define B_ 64
#define NV_ 21
#define BN_ 1344
#define L_ 2048
#define PATCH_ 16
#define PNUM_ 255
#define D_ 128
#define H_ 256
#define PRED_ 96
#define ROWS_ (BN_*PNUM_)      /* 342720 */
#define KHEAD_ (D_*PNUM_)      /* 32640  */
#define EPS_ 1e-5f
#define EMASCALE_ 0.7071067811865476f

// ---- scratch (no cudaMalloc allowed) ----
__device__ float g_bufA[ROWS_*D_];
__device__ float g_bufB[ROWS_*D_];
__device__ float g_u[BN_*KHEAD_];
__device__ float g_ema[D_*4];

__device__ __forceinline__ float2 ffma2(float2 a, float2 b, float2 c) {
    unsigned long long au = *reinterpret_cast<unsigned long long*>(&a);
    unsigned long long bu = *reinterpret_cast<unsigned long long*>(&b);
    unsigned long long cu = *reinterpret_cast<unsigned long long*>(&c);
    unsigned long long ru;
    asm("fma.rn.f32x2 %0, %1, %2, %3;" : "=l"(ru) : "l"(au), "l"(bu), "l"(cu));
    return *reinterpret_cast<float2*>(&ru);
}

// =====================================================================
// K0: EMA params -> per-(d,n) recurrence coefficients q, a
// =====================================================================
__global__ void k0_emaparam(const float* __restrict__ delta, const float* __restrict__ alpha,
                            const float* __restrict__ beta, const float* __restrict__ gamma)
{
    int d = threadIdx.x;
    if (d < D_) {
        #pragma unroll
        for (int n = 0; n < 2; n++) {
            int i = d*2 + n;
            float p = 1.f/(1.f + expf(-delta[i]));
            float q = 1.f - p * (1.f/(1.f + expf(-alpha[i])));
            float a = p * beta[i] * gamma[i] * EMASCALE_;
            g_ema[d*4 + n*2 + 0] = q;
            g_ema[d*4 + n*2 + 1] = a;
        }
    }
}

// =====================================================================
// K1: patch gather + feature-projection LEMblock (16->256->128 + res + LN)
// smem: h2[256][17] f2, p2[16][17] f2, w2s[256*128], ys[32][130], gs/bes
// =====================================================================
#define SM1_BYTES ((256*17 + 16*17)*8 + (256*128 + 32*130 + 256)*4)

__global__ __launch_bounds__(256, 1)
void k1_featproj(const float* __restrict__ x,
                 const float* __restrict__ w1, const float* __restrict__ b1,
                 const float* __restrict__ w2, const float* __restrict__ b2,
                 const float* __restrict__ wr, const float* __restrict__ br,
                 const float* __restrict__ g,  const float* __restrict__ be)
{
    extern __shared__ unsigned char smraw[];
    float2* h2 = (float2*)smraw;               // [256][17]
    float2* p2 = h2 + 256*17;                  // [16][17]
    float*  w2s = (float*)(p2 + 16*17);        // [256*128]
    float*  ys  = w2s + 256*128;               // [32][130]
    float*  gs  = ys + 32*130;                 // [128]
    float*  bes = gs + 128;                    // [128]

    int tid = threadIdx.x;
    for (int i = tid; i < 256*128; i += 256) w2s[i] = w2[i];
    if (tid < 128) { gs[tid] = g[tid]; bes[tid] = be[tid]; }

    float w1r[16];
    #pragma unroll
    for (int k = 0; k < 16; k++) w1r[k] = w1[k*256 + tid];
    float b1r = b1[tid];

    int cB = tid & 127, rg = tid >> 7;
    float wrr[16];
    #pragma unroll
    for (int k = 0; k < 16; k++) wrr[k] = wr[k*128 + cB];
    float bB = b2[cB] + br[cB];

    const int NTILES = ROWS_/32;   // 10710
    for (int tile = blockIdx.x; tile < NTILES; tile += gridDim.x) {
        int row0 = tile*32;
        __syncthreads();                                   // (1) protect reuse
        for (int i = tid; i < 32*16; i += 256) {
            int r = i >> 4, k = i & 15;
            int grow = row0 + r;
            int bn = grow / 255, p = grow - bn*255;
            float v = x[bn*L_ + p*8 + k];
            ((float*)(p2 + k*17 + (r>>1)))[r & 1] = v;
        }
        __syncthreads();                                   // (2)

        // phase A: h = relu(patch @ w1 + b1), col = tid, 32 rows packed
        float2 hacc[16];
        #pragma unroll
        for (int rp = 0; rp < 16; rp++) hacc[rp] = make_float2(b1r, b1r);
        #pragma unroll
        for (int k = 0; k < 16; k++) {
            float2 wv = make_float2(w1r[k], w1r[k]);
            #pragma unroll
            for (int rp = 0; rp < 16; rp++)
                hacc[rp] = ffma2(p2[k*17 + rp], wv, hacc[rp]);
        }
        #pragma unroll
        for (int rp = 0; rp < 16; rp++) {
            hacc[rp].x = fmaxf(hacc[rp].x, 0.f);
            hacc[rp].y = fmaxf(hacc[rp].y, 0.f);
        }

        // residual: patch @ wr + (b2+br), col = cB, 16 rows (this rg)
        float2 acc[8];
        #pragma unroll
        for (int j = 0; j < 8; j++) acc[j] = make_float2(bB, bB);
        #pragma unroll
        for (int k = 0; k < 16; k++) {
            float2 wv = make_float2(wrr[k], wrr[k]);
            #pragma unroll
            for (int j = 0; j < 8; j++)
                acc[j] = ffma2(p2[k*17 + rg*8 + j], wv, acc[j]);
        }
        __syncthreads();                                   // (3) prev h2 reads done
        #pragma unroll
        for (int rp = 0; rp < 16; rp++) h2[tid*17 + rp] = hacc[rp];
        __syncthreads();                                   // (4)

        // phase B: y += h @ w2
        #pragma unroll 2
        for (int k = 0; k < 256; k++) {
            float wv = w2s[k*128 + cB];
            float2 wv2 = make_float2(wv, wv);
            #pragma unroll
            for (int j = 0; j < 8; j++)
                acc[j] = ffma2(h2[k*17 + rg*8 + j], wv2, acc[j]);
        }
        #pragma unroll
        for (int j = 0; j < 8; j++) {
            ys[(rg*16 + 2*j  )*130 + cB] = acc[j].x;
            ys[(rg*16 + 2*j+1)*130 + cB] = acc[j].y;
        }
        __syncthreads();                                   // (5)

        // LayerNorm: 8 threads per row
        {
            int r = tid >> 3, seg = tid & 7;
            float s = 0.f, q = 0.f;
            #pragma unroll
            for (int i = 0; i < 16; i++) {
                float v = ys[r*130 + seg*16 + i];
                s += v; q += v*v;
            }
            #pragma unroll
            for (int m = 1; m < 8; m <<= 1) {
                s += __shfl_xor_sync(0xffffffffu, s, m);
                q += __shfl_xor_sync(0xffffffffu, q, m);
            }
            float mu = s * (1.f/128.f);
            float rstd = rsqrtf(q*(1.f/128.f) - mu*mu + EPS_);
            float* outp = g_bufA + (size_t)(row0 + r)*D_ + seg*16;
            #pragma unroll
            for (int i = 0; i < 16; i += 4) {
                float4 o;
                int c = seg*16 + i;
                o.x = (ys[r*130+c+0]-mu)*rstd*gs[c+0] + bes[c+0];
                o.y = (ys[r*130+c+1]-mu)*rstd*gs[c+1] + bes[c+1];
                o.z = (ys[r*130+c+2]-mu)*rstd*gs[c+2] + bes[c+2];
                o.w = (ys[r*130+c+3]-mu)*rstd*gs[c+3] + bes[c+3];
                *(float4*)(outp + i) = o;
            }
        }
    }
}

// =====================================================================
// K2: encoder LEMblock (128->128->128 + res + LN), runs twice
// smem: xh2[128][17] f2 (x then h), w1s/w2s/wrs 64KB each, ys, gs/bes
// =====================================================================
#define SM2_BYTES ((128*17)*8 + (3*128*128 + 32*130 + 256)*4)

__global__ __launch_bounds__(256, 1)
void k2_encoder(const float* __restrict__ ew1, const float* __restrict__ eb1,
                const float* __restrict__ ew2, const float* __restrict__ eb2,
                const float* __restrict__ ewr, const float* __restrict__ ebr,
                const float* __restrict__ eg,  const float* __restrict__ ebe,
                int layer)
{
    extern __shared__ unsigned char smraw[];
    float2* xh2 = (float2*)smraw;              // [128][17]
    float* w1s = (float*)(xh2 + 128*17);
    float* w2s = w1s + 128*128;
    float* wrs = w2s + 128*128;
    float* ys  = wrs + 128*128;                // [32][130]
    float* gs  = ys + 32*130;
    float* bes = gs + 128;

    const float* w1 = ew1 + layer*D_*D_;
    const float* w2 = ew2 + layer*D_*D_;
    const float* wr = ewr + layer*D_*D_;
    const float* zin  = layer ? g_bufB : g_bufA;
    float*       zout = layer ? g_bufA : g_bufB;

    int tid = threadIdx.x;
    for (int i = tid; i < 128*128; i += 256) {
        w1s[i] = w1[i]; w2s[i] = w2[i]; wrs[i] = wr[i];
    }
    if (tid < 128) { gs[tid] = eg[layer*128 + tid]; bes[tid] = ebe[layer*128 + tid]; }
    int cB = tid & 127, rg = tid >> 7;
    float b1r = eb1[layer*128 + cB];
    float bB  = eb2[layer*128 + cB] + ebr[layer*128 + cB];

    const int NTILES = ROWS_/32;
    for (int tile = blockIdx.x; tile < NTILES; tile += gridDim.x) {
        size_t row0 = (size_t)tile*32;
        __syncthreads();                                   // (1)
        for (int i = tid; i < 32*128; i += 256) {
            int r = i >> 7, c = i & 127;
            ((float*)(xh2 + c*17 + (r>>1)))[r & 1] = zin[(row0 + r)*D_ + c];
        }
        __syncthreads();                                   // (2)

        // residual and hidden together (share x loads)
        float2 racc[8], hacc[8];
        #pragma unroll
        for (int j = 0; j < 8; j++) { racc[j] = make_float2(bB, bB); hacc[j] = make_float2(b1r, b1r); }
        #pragma unroll 2
        for (int k = 0; k < 128; k++) {
            float wrv = wrs[k*128 + cB];
            float w1v = w1s[k*128 + cB];
            float2 wr2 = make_float2(wrv, wrv);
            float2 w12 = make_float2(w1v, w1v);
            #pragma unroll
            for (int j = 0; j < 8; j++) {
                float2 xv = xh2[k*17 + rg*8 + j];
                racc[j] = ffma2(xv, wr2, racc[j]);
                hacc[j] = ffma2(xv, w12, hacc[j]);
            }
        }
        #pragma unroll
        for (int j = 0; j < 8; j++) {
            hacc[j].x = fmaxf(hacc[j].x, 0.f);
            hacc[j].y = fmaxf(hacc[j].y, 0.f);
        }
        __syncthreads();                                   // (3) everyone done reading x
        #pragma unroll
        for (int j = 0; j < 8; j++) xh2[cB*17 + rg*8 + j] = hacc[j];
        __syncthreads();                                   // (4)

        // phase B: y = racc + h @ w2
        #pragma unroll 2
        for (int k = 0; k < 128; k++) {
            float wv = w2s[k*128 + cB];
            float2 wv2 = make_float2(wv, wv);
            #pragma unroll
            for (int j = 0; j < 8; j++)
                racc[j] = ffma2(xh2[k*17 + rg*8 + j], wv2, racc[j]);
        }
        #pragma unroll
        for (int j = 0; j < 8; j++) {
            ys[(rg*16 + 2*j  )*130 + cB] = racc[j].x;
            ys[(rg*16 + 2*j+1)*130 + cB] = racc[j].y;
        }
        __syncthreads();                                   // (5)

        {
            int r = tid >> 3, seg = tid & 7;
            float s = 0.f, q = 0.f;
            #pragma unroll
            for (int i = 0; i < 16; i++) {
                float v = ys[r*130 + seg*16 + i];
                s += v; q += v*v;
            }
            #pragma unroll
            for (int m = 1; m < 8; m <<= 1) {
                s += __shfl_xor_sync(0xffffffffu, s, m);
                q += __shfl_xor_sync(0xffffffffu, q, m);
            }
            float mu = s * (1.f/128.f);
            float rstd = rsqrtf(q*(1.f/128.f) - mu*mu + EPS_);
            float* outp = zout + (row0 + r)*D_ + seg*16;
            #pragma unroll
            for (int i = 0; i < 16; i += 4) {
                float4 o;
                int c = seg*16 + i;
                o.x = (ys[r*130+c+0]-mu)*rstd*gs[c+0] + bes[c+0];
                o.y = (ys[r*130+c+1]-mu)*rstd*gs[c+1] + bes[c+1];
                o.z = (ys[r*130+c+2]-mu)*rstd*gs[c+2] + bes[c+2];
                o.w = (ys[r*130+c+3]-mu)*rstd*gs[c+3] + bes[c+3];
                *(float4*)(outp + i) = o;
            }
        }
    }
}

// =====================================================================
// K4: MultiHeadEMA as 2-state linear recurrence + residual + SiLU,
//     transposed write into head layout u[bn][d*255 + t]
// =====================================================================
__global__ void k4_ema(const float* __restrict__ omega)
{
    __shared__ float tile[128*65];
    int bn = blockIdx.x, d = threadIdx.x;
    float q0 = g_ema[d*4+0], a0 = g_ema[d*4+1];
    float q1 = g_ema[d*4+2], a1 = g_ema[d*4+3];
    float om = omega[d];
    const float* src = g_bufA + (size_t)bn*PNUM_*D_ + d;
    float* dst = g_u + (size_t)bn*KHEAD_;
    float s0 = 0.f, s1 = 0.f;
    for (int chunk = 0; chunk < 4; chunk++) {
        int tbase = chunk*64;
        int tn = (PNUM_ - tbase < 64) ? (PNUM_ - tbase) : 64;
        #pragma unroll 4
        for (int i = 0; i < tn; i++) {
            float xv = src[(size_t)(tbase + i)*D_];
            s0 = fmaf(s0, q0, xv);
            s1 = fmaf(s1, q1, xv);
            float v = fmaf(om, xv, fmaf(a0, s0, a1*s1));
            tile[d*65 + i] = v * (1.f/(1.f + __expf(-v)));
        }
        __syncthreads();
        for (int i = d; i < 128*64; i += 128) {
            int dd = i >> 6, tt = i & 63;
            if (tt < tn) dst[dd*PNUM_ + tbase + tt] = tile[dd*65 + tt];
        }
        __syncthreads();
    }
}

// =====================================================================
// K5: head GEMM [1344 x 32640] @ [32640 x 96], K-split=5 with atomics
// =====================================================================
__global__ void k5_init(const float* __restrict__ hb, float* __restrict__ out)
{
    int i = blockIdx.x*blockDim.x + threadIdx.x;
    if (i < BN_*PRED_) out[i] = hb[i % PRED_];
}

__global__ __launch_bounds__(192)
void k5_head(const float* __restrict__ hw, float* __restrict__ out)
{
    __shared__ float2 u2[64*17];
    __shared__ float ws[64*96];
    int tid = threadIdx.x;
    int cB = tid % 96, rg = tid / 96;
    int row0 = blockIdx.x * 32;
    float2 acc[8];
    #pragma unroll
    for (int j = 0; j < 8; j++) acc[j] = make_float2(0.f, 0.f);
    for (int ch = 0; ch < 102; ch++) {
        int k0 = (blockIdx.y * 102 + ch) * 64;
        __syncthreads();
        for (int i = tid; i < 32*64; i += 192) {
            int r = i >> 6, kk = i & 63;
            ((float*)(u2 + kk*17 + (r>>1)))[r & 1] = g_u[(size_t)(row0+r)*KHEAD_ + k0 + kk];
        }
        for (int i = tid; i < 64*96; i += 192) ws[i] = hw[(size_t)k0*96 + i];
        __syncthreads();
        #pragma unroll 2
        for (int kk = 0; kk < 64; kk++) {
            float wv = ws[kk*96 + cB];
            float2 wv2 = make_float2(wv, wv);
            #pragma unroll
            for (int j = 0; j < 8; j++)
                acc[j] = ffma2(u2[kk*17 + rg*8 + j], wv2, acc[j]);
        }
    }
    #pragma unroll
    for (int j = 0; j < 8; j++) {
        int r = row0 + rg*16 + 2*j;
        atomicAdd(&out[r*PRED_ + cB],     acc[j].x);
        atomicAdd(&out[(r+1)*PRED_ + cB], acc[j].y);
    }
}

// =====================================================================
extern "C" void kernel_launch(void* const* d_in, const int* in_sizes, int n_in,
                              void* d_out, int out_size)
{
    const float* x       = (const float*)d_in[0];
    const float* fp_w1   = (const float*)d_in[1];
    const float* fp_b1   = (const float*)d_in[2];
    const float* fp_w2   = (const float*)d_in[3];
    const float* fp_b2   = (const float*)d_in[4];
    const float* fp_wr   = (const float*)d_in[5];
    const float* fp_br   = (const float*)d_in[6];
    const float* fp_g    = (const float*)d_in[7];
    const float* fp_be   = (const float*)d_in[8];
    const float* enc_w1  = (const float*)d_in[9];
    const float* enc_b1  = (const float*)d_in[10];
    const float* enc_w2  = (const float*)d_in[11];
    const float* enc_b2  = (const float*)d_in[12];
    const float* enc_wr  = (const float*)d_in[13];
    const float* enc_br  = (const float*)d_in[14];
    const float* enc_g   = (const float*)d_in[15];
    const float* enc_be  = (const float*)d_in[16];
    const float* e_delta = (const float*)d_in[17];
    const float* e_alpha = (const float*)d_in[18];
    const float* e_beta  = (const float*)d_in[19];
    const float* e_gamma = (const float*)d_in[20];
    const float* e_omega = (const float*)d_in[21];
    const float* head_w  = (const float*)d_in[22];
    const float* head_b  = (const float*)d_in[23];
    float* out = (float*)d_out;

    cudaFuncSetAttribute(k1_featproj, cudaFuncAttributeMaxDynamicSharedMemorySize, SM1_BYTES);
    cudaFuncSetAttribute(k2_encoder,  cudaFuncAttributeMaxDynamicSharedMemorySize, SM2_BYTES);

    k0_emaparam<<<1, 128>>>(e_delta, e_alpha, e_beta, e_gamma);
    k1_featproj<<<148, 256, SM1_BYTES>>>(x, fp_w1, fp_b1, fp_w2, fp_b2, fp_wr, fp_br, fp_g, fp_be);
    k2_encoder<<<148, 256, SM2_BYTES>>>(enc_w1, enc_b1, enc_w2, enc_b2, enc_wr, enc_br, enc_g, enc_be, 0);
    k2_encoder<<<148, 256, SM2_BYTES>>>(enc_w1, enc_b1, enc_w2, enc_b2, enc_wr, enc_br, enc_g, enc_be, 1);
    k4_ema<<<BN_, 128>>>(e_omega);
    k5_init<<<(BN_*PRED_ + 255)/256, 256>>>(head_b, out);
    k5_head<<<dim3(42, 5), 192>>>(head_w, out);
}